// round 7
// baseline (speedup 1.0000x reference)
#include <cuda_runtime.h>

// KAN_Convolutional_Layer: B=8, CIN=4, H=W=64, OUT=8, K2=9, G=8, Ho=Wo=62
// Strip-mined fused kernel, 128 blocks x 512 threads.
// R7 = R6 with bank-conflict-free shared strides:
//   WCG  = 148 words: weight LDS.128 -> 8 distinct bank quads, 1 wavefront/instr
//   PSTR = 388 words: tv float4     -> optimal 4 wavefronts/instr

#define B_    8
#define CIN_  4
#define H_    64
#define W_    64
#define OUT_  8
#define K2_   9
#define G_    8
#define HO_   62
#define WO_   62
#define R2_   39.0625f     // R^2 folded into weights

#define TILW  36           // 32 px + 2 halo + 2 pad (keeps LDS.128 aligned)
#define TILH  10
#define NPOS  (TILH*TILW)  // 360
#define PSTR  388          // 4*97, 97 % 8 == 1 -> quad spread (q+sub) mod 8
#define WCG   148          // 4*37, 37 % 8 == 5 -> q*5 mod 8 all distinct
#define NTHR  512

typedef unsigned long long u64;

__device__ __forceinline__ u64 pack2(float lo, float hi) {
    u64 r;
    asm("mov.b64 %0, {%1, %2};" : "=l"(r) : "f"(lo), "f"(hi));
    return r;
}
__device__ __forceinline__ void unpack2(u64 v, float& lo, float& hi) {
    asm("mov.b64 {%0, %1}, %2;" : "=f"(lo), "=f"(hi) : "l"(v));
}
__device__ __forceinline__ u64 fma2(u64 a, u64 b, u64 c) {
    u64 d;
    asm("fma.rn.f32x2 %0, %1, %2, %3;" : "=l"(d) : "l"(a), "l"(b), "l"(c));
    return d;
}
__device__ __forceinline__ u64 add2(u64 a, u64 b) {
    u64 d;
    asm("add.rn.f32x2 %0, %1, %2;" : "=l"(d) : "l"(a), "l"(b));
    return d;
}

__global__ void __launch_bounds__(NTHR, 1)
kan_fused_kernel(const float* __restrict__ x,
                 const float* __restrict__ phase_low,
                 const float* __restrict__ phase_high,
                 const float* __restrict__ weight,
                 const float* __restrict__ bias,
                 float* __restrict__ out) {
    __shared__ __align__(16) float tsh[16 * PSTR];   // 24.8 KB (one c-pair stage)
    __shared__ __align__(16) float wsh[32 * WCG];    // 18.9 KB, dup'd weights
    __shared__ float bsh[OUT_];

    const int b   = blockIdx.z;
    const int x0  = blockIdx.x * 32;
    const int y0  = blockIdx.y * 8;
    const int tid = threadIdx.x;

    // ---- duplicated weights: wsh[cg*WCG + f*16 + o*2 + {0,1}] = w*R^2
#pragma unroll
    for (int it = 0; it < 5; it++) {
        int i = tid + it * NTHR;
        if (i < 32 * K2_ * OUT_) {
            int o  = i & 7;
            int f  = (i >> 3) % K2_;
            int cg = i / (K2_ * OUT_);
            int g  = cg & 7;
            int c  = cg >> 3;
            float wv = weight[((o * CIN_ + c) * K2_ + f) * G_ + g] * R2_;
            int base = cg * WCG + f * 16 + o * 2;
            wsh[base]     = wv;
            wsh[base + 1] = wv;
        }
    }
    if (tid < OUT_) {
        float s = 0.0f;
#pragma unroll
        for (int c = 0; c < CIN_; c++) s += bias[tid * CIN_ + c];
        bsh[tid] = s;
    }

    float pl[G_], ph[G_];
#pragma unroll
    for (int g = 0; g < G_; g++) {
        pl[g] = __ldg(&phase_low[g]);   // broadcast over (o,c,f) by construction
        ph[g] = __ldg(&phase_high[g]);
    }

    // ---- lane decomposition
    const int w   = tid >> 5;
    const int l   = tid & 31;
    const int q   = l >> 2;             // 0..7  (cg group)
    const int sub = l & 3;
    const int sy  = w >> 1;             // strip row 0..7
    const int sx  = (w & 1) * 4 + sub;  // strip col 0..7 (strip = 4 px wide)

    u64 acc[OUT_][2];
#pragma unroll
    for (int o = 0; o < OUT_; o++) { acc[o][0] = 0; acc[o][1] = 0; }

#pragma unroll
    for (int s = 0; s < 2; s++) {       // c-pair stages {0,1}, {2,3}
        __syncthreads();                // prior stage reads done
        // -- spline fill: 2 c-planes x 8 g, 360 positions each
#pragma unroll
        for (int it = 0; it < 2; it++) {
            int i = tid + it * NTHR;
            if (i < 2 * NPOS) {
                int cl  = i >= NPOS;
                int pos = i - cl * NPOS;
                int row = pos / TILW;
                int col = pos - row * TILW;
                int gy = y0 + row, gx = x0 + col;
                float xv = 0.0f;
                if (gy < H_ && gx < W_)
                    xv = __ldg(&x[((b * CIN_ + 2 * s + cl) * H_ + gy) * W_ + gx]);
#pragma unroll
                for (int g = 0; g < G_; g++) {
                    float a = fmaxf(xv - pl[g], 0.0f);
                    float d = fmaxf(ph[g] - xv, 0.0f);
                    float m = a * d;
                    tsh[(cl * G_ + g) * PSTR + pos] = m * m;   // R^2 in weights
                }
            }
        }
        __syncthreads();

        // -- conv: q handles planes q and q+8 of this stage
#pragma unroll
        for (int i = 0; i < 2; i++) {
            const int p = q + 8 * i;                     // plane 0..15
            const float* pb = tsh + p * PSTR + sy * TILW + 4 * sx;  // 16B aligned
            const float* wp = wsh + (s * 16 + p) * WCG;

            // tv: 3 rows x 6 cols; pairs per (row, fj)
            u64 pr[3][3][2];
#pragma unroll
            for (int r = 0; r < 3; r++) {
                float4 v4 = *reinterpret_cast<const float4*>(pb + r * TILW);
                float2 v2 = *reinterpret_cast<const float2*>(pb + r * TILW + 4);
                u64 p01 = pack2(v4.x, v4.y);
                u64 p23 = pack2(v4.z, v4.w);
                u64 p45 = pack2(v2.x, v2.y);
                pr[r][0][0] = p01;               pr[r][0][1] = p23;
                pr[r][1][0] = pack2(v4.y, v4.z); pr[r][1][1] = pack2(v4.w, v2.x);
                pr[r][2][0] = p23;               pr[r][2][1] = p45;
            }

#pragma unroll
            for (int fi = 0; fi < 3; fi++) {
#pragma unroll
                for (int fj = 0; fj < 3; fj++) {
                    const ulonglong2* wv =
                        reinterpret_cast<const ulonglong2*>(wp + (fi * 3 + fj) * 16);
                    ulonglong2 w01 = wv[0];   // dup'd o0, o1
                    ulonglong2 w23 = wv[1];
                    ulonglong2 w45 = wv[2];
                    ulonglong2 w67 = wv[3];
                    u64 ta = pr[fi][fj][0];   // (px0, px1)
                    u64 tb = pr[fi][fj][1];   // (px2, px3)
                    acc[0][0] = fma2(ta, w01.x, acc[0][0]);
                    acc[0][1] = fma2(tb, w01.x, acc[0][1]);
                    acc[1][0] = fma2(ta, w01.y, acc[1][0]);
                    acc[1][1] = fma2(tb, w01.y, acc[1][1]);
                    acc[2][0] = fma2(ta, w23.x, acc[2][0]);
                    acc[2][1] = fma2(tb, w23.x, acc[2][1]);
                    acc[3][0] = fma2(ta, w23.y, acc[3][0]);
                    acc[3][1] = fma2(tb, w23.y, acc[3][1]);
                    acc[4][0] = fma2(ta, w45.x, acc[4][0]);
                    acc[4][1] = fma2(tb, w45.x, acc[4][1]);
                    acc[5][0] = fma2(ta, w45.y, acc[5][0]);
                    acc[5][1] = fma2(tb, w45.y, acc[5][1]);
                    acc[6][0] = fma2(ta, w67.x, acc[6][0]);
                    acc[6][1] = fma2(tb, w67.x, acc[6][1]);
                    acc[7][0] = fma2(ta, w67.y, acc[7][0]);
                    acc[7][1] = fma2(tb, w67.y, acc[7][1]);
                }
            }
        }
    }

    // ---- butterfly half-exchange reduction over the 8 q-groups
    u64 A[16];
#pragma unroll
    for (int o = 0; o < OUT_; o++) { A[o * 2] = acc[o][0]; A[o * 2 + 1] = acc[o][1]; }

#pragma unroll
    for (int lvl = 0; lvl < 3; lvl++) {
        const int mask = 4 << lvl;
        const int half = 8 >> lvl;
        const bool bit = (q >> lvl) & 1;
#pragma unroll
        for (int j = 0; j < 8; j++) {
            if (j < half) {
                u64 lo = A[j], hi = A[half + j];
                u64 sent = bit ? lo : hi;
                u64 rec  = __shfl_xor_sync(0xffffffffu, sent, mask);
                A[j] = add2(bit ? hi : lo, rec);
            }
        }
    }
    // lane q holds output channel o = bitrev3(q): A[0]=(px0,px1), A[1]=(px2,px3)
    const int o = ((q & 1) << 2) | (q & 2) | (q >> 2);

    float v0, v1, v2, v3;
    unpack2(A[0], v0, v1);
    unpack2(A[1], v2, v3);
    const float bo = bsh[o];
    const int oy  = y0 + sy;
    const int ox0 = x0 + 4 * sx;
    if (oy < HO_) {
        float* op = out + ((b * OUT_ + o) * HO_ + oy) * WO_ + ox0;
        if (ox0 + 0 < WO_) op[0] = v0 + bo;
        if (ox0 + 1 < WO_) op[1] = v1 + bo;
        if (ox0 + 2 < WO_) op[2] = v2 + bo;
        if (ox0 + 3 < WO_) op[3] = v3 + bo;
    }
}

// ---------------------------------------------------------------------------
extern "C" void kernel_launch(void* const* d_in, const int* in_sizes, int n_in,
                              void* d_out, int out_size) {
    const float* x          = (const float*)d_in[0];
    const float* phase_low  = (const float*)d_in[1];
    const float* phase_high = (const float*)d_in[2];
    const float* weight     = (const float*)d_in[3];
    const float* bias       = (const float*)d_in[4];
    float* out = (float*)d_out;

    dim3 grid(2, 8, B_);                 // 128 blocks x 512 threads
    kan_fused_kernel<<<grid, NTHR>>>(x, phase_low, phase_high, weight, bias, out);
}